// round 7
// baseline (speedup 1.0000x reference)
#include <cuda_runtime.h>
#include <cstdint>

// TrueHigherOrderAttention — degenerate-mask reduction.
// The reference mask forces j==i and k==i, so the (j,k) softmax is an exact
// one-hot at (i,i,i):   out = ((x @ Wv1^T) .* (x @ Wv2^T)) @ Wc^T
//
// R7: 3xTF32 mma.sync pipeline with the hi/lo tf32 split HOISTED out of the
// GEMM kernels. A pre-split pass writes hi(tf32-bits)/lo(residual) planes of
// x/Wv1/Wv2/Wc into device buffers, already permuted into MMA-fragment word
// order (word p = 2*(k&3)+(k>>2) within each 8-k group). GEMM loaders are
// pure LDG.128->STS.128 copies (conflict-free with BLK=264); compute loop is
// the proven R6 m16n8k8 3-term loop. Stage1 writes tmp pre-split so stage2
// also needs zero conversions.

constexpr int T    = 256;
constexpr int C    = 512;
constexpr int KC   = 64;
constexpr int NCH  = 8;          // 512 / 64
constexpr int BLK  = 264;        // words per 8-k block (32 rows x 8 + pad 8)
constexpr int TIER = 8 * BLK;    // 2112 words: hi tile or lo tile per chunk

constexpr int A_HI  = 0;
constexpr int B1_HI = 2 * TIER;
constexpr int B2_HI = 4 * TIER;

// pre-split planes (hi = tf32 bit pattern stored as float, lo = residual)
__device__ float g_xh [T * C], g_xl [T * C];
__device__ float g_w1h[C * C], g_w1l[C * C];
__device__ float g_w2h[C * C], g_w2l[C * C];
__device__ float g_wch[C * C], g_wcl[C * C];
__device__ float g_th [T * C], g_tl [T * C];   // stage1 output, pre-split

__device__ __forceinline__ uint32_t f2tf32(float x)
{
    uint32_t r;
    asm("cvt.rna.tf32.f32 %0, %1;" : "=r"(r) : "f"(x));
    return r;
}

__device__ __forceinline__ void mma8(float* d, const uint32_t* a, const uint32_t* b)
{
    asm("mma.sync.aligned.m16n8k8.row.col.f32.tf32.tf32.f32 "
        "{%0,%1,%2,%3}, {%4,%5,%6,%7}, {%8,%9}, {%0,%1,%2,%3};"
        : "+f"(d[0]), "+f"(d[1]), "+f"(d[2]), "+f"(d[3])
        : "r"(a[0]), "r"(a[1]), "r"(a[2]), "r"(a[3]),
          "r"(b[0]), "r"(b[1]));
}

// Split src into hi/lo planes, permuted within each 8-float group:
// word order [v0,v4,v1,v5,v2,v6,v3,v7]  (p(k) = 2*(k&3) + (k>>2)).
__global__ __launch_bounds__(256)
void split_kernel(const float* __restrict__ src,
                  float* __restrict__ hi, float* __restrict__ lo)
{
    const int g = blockIdx.x * 256 + threadIdx.x;    // 8-float group index
    const float4 a = *(const float4*)&src[8 * g];
    const float4 b = *(const float4*)&src[8 * g + 4];
    const float v[8] = {a.x, a.y, a.z, a.w, b.x, b.y, b.z, b.w};
    uint32_t h[8]; float l[8];
#pragma unroll
    for (int k = 0; k < 8; k++) {
        h[k] = f2tf32(v[k]);
        l[k] = v[k] - __uint_as_float(h[k]);
    }
    *(uint4*) &hi[8 * g]     = make_uint4(h[0], h[4], h[1], h[5]);
    *(uint4*) &hi[8 * g + 4] = make_uint4(h[2], h[6], h[3], h[7]);
    *(float4*)&lo[8 * g]     = make_float4(l[0], l[4], l[1], l[5]);
    *(float4*)&lo[8 * g + 4] = make_float4(l[2], l[6], l[3], l[7]);
}

// OUT = (X @ W1^T) [ .* (X @ W2^T) if DUAL ]  on a 32x32 tile, 3xTF32.
// All inputs are pre-split/pre-permuted planes. DUAL=1 writes OUTa/OUTb =
// hi/lo planes of the result (for stage2); DUAL=0 writes plain floats to OUTa.
template <bool DUAL>
__global__ __launch_bounds__(256)
void gemm_mma_kernel(const float* __restrict__ Xhi, const float* __restrict__ Xlo,
                     const float* __restrict__ W1hi, const float* __restrict__ W1lo,
                     const float* __restrict__ W2hi, const float* __restrict__ W2lo,
                     float* __restrict__ OUTa, float* __restrict__ OUTb)
{
    extern __shared__ uint32_t sm[];

    const int i0   = blockIdx.x * 32;
    const int n0   = blockIdx.y * 32;
    const int tid  = threadIdx.x;
    const int lane = tid & 31;
    const int wid  = tid >> 5;

    // ---- loader: row = tid>>3 (32 rows), quad q = (tid&7) + 8*it ----
    const int lrow = tid >> 3;
    const int q0   = tid & 7;

    uint4 xh[2], xl[2], w1h[2], w1l[2], w2h[2], w2l[2];
    auto gload = [&](int kb) {
#pragma unroll
        for (int it = 0; it < 2; it++) {
            const int q    = q0 + 8 * it;
            const int xoff = (i0 + lrow) * C + kb + 4 * q;
            const int woff = (n0 + lrow) * C + kb + 4 * q;
            xh [it] = *(const uint4*)&Xhi [xoff];
            xl [it] = *(const uint4*)&Xlo [xoff];
            w1h[it] = *(const uint4*)&W1hi[woff];
            w1l[it] = *(const uint4*)&W1lo[woff];
            if (DUAL) {
                w2h[it] = *(const uint4*)&W2hi[woff];
                w2l[it] = *(const uint4*)&W2lo[woff];
            }
        }
    };
    gload(0);

    // ---- compute mapping: 8 warps = 2(m) x 4(n); warp tile m16 x n8 ----
    const int M0 = (wid >> 2) * 16;
    const int N0 = (wid & 3) * 8;
    const int ar = (M0 + (lane >> 2)) * 8 + 2 * (lane & 3);
    const int br = (N0 + (lane >> 2)) * 8 + 2 * (lane & 3);

    float p[3][4] = {}, q[3][4] = {};

    for (int ch = 0; ch < NCH; ch++) {
        if (ch) __syncthreads();
#pragma unroll
        for (int it = 0; it < 2; it++) {
            const int qq = q0 + 8 * it;
            const int d  = (qq >> 1) * BLK + lrow * 8 + 4 * (qq & 1);
            *(uint4*)&sm[A_HI  + d]        = xh [it];
            *(uint4*)&sm[A_HI  + TIER + d] = xl [it];
            *(uint4*)&sm[B1_HI + d]        = w1h[it];
            *(uint4*)&sm[B1_HI + TIER + d] = w1l[it];
            if (DUAL) {
                *(uint4*)&sm[B2_HI + d]        = w2h[it];
                *(uint4*)&sm[B2_HI + TIER + d] = w2l[it];
            }
        }
        __syncthreads();
        if (ch + 1 < NCH) gload((ch + 1) * KC);   // prefetch under compute

#pragma unroll
        for (int s = 0; s < 8; s++) {
            const int o = s * BLK;
            const uint2 h02 = *(const uint2*)&sm[A_HI + o + ar];
            const uint2 h13 = *(const uint2*)&sm[A_HI + o + ar + 64];
            const uint2 l02 = *(const uint2*)&sm[A_HI + TIER + o + ar];
            const uint2 l13 = *(const uint2*)&sm[A_HI + TIER + o + ar + 64];
            const uint32_t Ah[4] = {h02.x, h13.x, h02.y, h13.y};
            const uint32_t Al[4] = {l02.x, l13.x, l02.y, l13.y};

            const uint2 b1h = *(const uint2*)&sm[B1_HI + o + br];
            const uint2 b1l = *(const uint2*)&sm[B1_HI + TIER + o + br];
            const uint32_t B1h[2] = {b1h.x, b1h.y};
            const uint32_t B1l[2] = {b1l.x, b1l.y};

            mma8(p[0], Ah, B1h);
            mma8(p[1], Ah, B1l);
            mma8(p[2], Al, B1h);

            if (DUAL) {
                const uint2 b2h = *(const uint2*)&sm[B2_HI + o + br];
                const uint2 b2l = *(const uint2*)&sm[B2_HI + TIER + o + br];
                const uint32_t B2h[2] = {b2h.x, b2h.y};
                const uint32_t B2l[2] = {b2l.x, b2l.y};
                mma8(q[0], Ah, B2h);
                mma8(q[1], Ah, B2l);
                mma8(q[2], Al, B2h);
            }
        }
    }

    // ---- epilogue ----
    float P[4], Q[4];
#pragma unroll
    for (int i = 0; i < 4; i++) {
        P[i] = p[0][i] + p[1][i] + p[2][i];
        if (DUAL) Q[i] = q[0][i] + q[1][i] + q[2][i];
    }
    const int row = i0 + M0 + (lane >> 2);
    const int col = n0 + N0 + 2 * (lane & 3);

    if (DUAL) {
        // write tmp pre-split + permuted (hi/lo planes)
#pragma unroll
        for (int i = 0; i < 4; i++) {
            const int r = row + (i >> 1) * 8;
            const int c = col + (i & 1);
            const float v = P[i] * Q[i];
            const uint32_t h = f2tf32(v);
            const int pos = r * C + (c & ~7) + 2 * (c & 3) + ((c >> 2) & 1);
            OUTa[pos] = __uint_as_float(h);
            OUTb[pos] = v - __uint_as_float(h);
        }
    } else {
        *(float2*)&OUTa[ row      * C + col] = make_float2(P[0], P[1]);
        *(float2*)&OUTa[(row + 8) * C + col] = make_float2(P[2], P[3]);
    }
}

extern "C" void kernel_launch(void* const* d_in, const int* in_sizes, int n_in,
                              void* d_out, int out_size)
{
    // metadata order: x, Wq, Wk1, Wk2, Wv1, Wv2, Wc
    const float* x   = (const float*)d_in[0];
    const float* Wv1 = (const float*)d_in[4];
    const float* Wv2 = (const float*)d_in[5];
    const float* Wc  = (const float*)d_in[6];
    float* out = (float*)d_out;

    float *xh, *xl, *w1h, *w1l, *w2h, *w2l, *wch, *wcl, *th, *tl;
    cudaGetSymbolAddress((void**)&xh,  g_xh);
    cudaGetSymbolAddress((void**)&xl,  g_xl);
    cudaGetSymbolAddress((void**)&w1h, g_w1h);
    cudaGetSymbolAddress((void**)&w1l, g_w1l);
    cudaGetSymbolAddress((void**)&w2h, g_w2h);
    cudaGetSymbolAddress((void**)&w2l, g_w2l);
    cudaGetSymbolAddress((void**)&wch, g_wch);
    cudaGetSymbolAddress((void**)&wcl, g_wcl);
    cudaGetSymbolAddress((void**)&th,  g_th);
    cudaGetSymbolAddress((void**)&tl,  g_tl);

    const int sm1 = 6 * TIER * 4;   // 50688 B
    const int sm2 = 4 * TIER * 4;   // 33792 B
    cudaFuncSetAttribute(gemm_mma_kernel<true>,
                         cudaFuncAttributeMaxDynamicSharedMemorySize, sm1);
    cudaFuncSetAttribute(gemm_mma_kernel<false>,
                         cudaFuncAttributeMaxDynamicSharedMemorySize, sm2);

    // pre-split pass (x: 16384 groups -> 64 blocks; each W: 32768 -> 128)
    split_kernel<<< 64, 256>>>(x,   xh,  xl);
    split_kernel<<<128, 256>>>(Wv1, w1h, w1l);
    split_kernel<<<128, 256>>>(Wv2, w2h, w2l);
    split_kernel<<<128, 256>>>(Wc,  wch, wcl);

    dim3 grid(T / 32, C / 32);   // 8 x 16 = 128 CTAs
    gemm_mma_kernel<true ><<<grid, 256, sm1>>>(xh, xl, w1h, w1l, w2h, w2l, th, tl);
    gemm_mma_kernel<false><<<grid, 256, sm2>>>(th, tl, wch, wcl, nullptr, nullptr, out, nullptr);
}

// round 9
// speedup vs baseline: 1.5625x; 1.5625x over previous
#include <cuda_runtime.h>
#include <cstdint>

// TrueHigherOrderAttention — degenerate-mask reduction.
// The reference mask forces j==i and k==i, so the (j,k) softmax is an exact
// one-hot at (i,i,i):   out = ((x @ Wv1^T) .* (x @ Wv2^T)) @ Wc^T
//
// R8: R6 (21.3us) skeleton — 2 launches, in-kernel 3xTF32 hi/lo split,
// m16n8k8 tf32 mma.sync, 32x32 CTA tile — but with 512-thread CTAs and
// 2-way in-CTA K-split: 16 warps = 2(m) x 4(n) x 2(kz), each warp covers
// half the 8-k steps of every chunk; partials merged once via smem.
// Doubles warps/SMSP (2->4) to cover LDS->MMA latency; loader work per
// thread halves. Fragment addressing identical to R6.

constexpr int T    = 256;
constexpr int C    = 512;
constexpr int KC   = 64;
constexpr int NCH  = 8;          // 512 / 64
constexpr int BLK  = 264;        // words per 8-k block (32 rows x 8 + pad)
constexpr int TIER = 8 * BLK;    // hi -> lo offset within a tile

constexpr int A_HI  = 0;
constexpr int B1_HI = 2 * TIER;
constexpr int B2_HI = 4 * TIER;

__device__ float g_tmp[T * C];

__device__ __forceinline__ uint32_t f2tf32(float x)
{
    uint32_t r;
    asm("cvt.rna.tf32.f32 %0, %1;" : "=r"(r) : "f"(x));
    return r;
}

__device__ __forceinline__ void mma8(float* d, const uint32_t* a, const uint32_t* b)
{
    asm("mma.sync.aligned.m16n8k8.row.col.f32.tf32.tf32.f32 "
        "{%0,%1,%2,%3}, {%4,%5,%6,%7}, {%8,%9}, {%0,%1,%2,%3};"
        : "+f"(d[0]), "+f"(d[1]), "+f"(d[2]), "+f"(d[3])
        : "r"(a[0]), "r"(a[1]), "r"(a[2]), "r"(a[3]),
          "r"(b[0]), "r"(b[1]));
}

// OUT = (X @ W1^T) [ .* (X @ W2^T) if DUAL ]  on a 32x32 tile, 3xTF32.
// X: [M x C] row-major; W: [C x C] row-major (output col n = row n of W).
template <bool DUAL>
__global__ __launch_bounds__(512)
void gemm_mma_kernel(const float* __restrict__ X,
                     const float* __restrict__ W1,
                     const float* __restrict__ W2,
                     float* __restrict__ OUT)
{
    extern __shared__ uint32_t sm[];

    const int i0   = blockIdx.x * 32;
    const int n0   = blockIdx.y * 32;
    const int tid  = threadIdx.x;
    const int lane = tid & 31;
    const int wid  = tid >> 5;            // 0..15
    const int z    = wid >> 3;            // k-half: warps 0-7 -> 0, 8-15 -> 1
    const int mw   = wid & 7;             // 2(m) x 4(n) position

    // ---- loader: 512 threads stage one 64-k chunk; 1 float4/tile/thread ----
    const int lrow = tid >> 4;            // 0..31
    const int q0   = tid & 15;            // quad (4k) within chunk

    float4 xr, w1r, w2r;
    auto gload = [&](int kb) {
        xr  = *(const float4*)&X [(i0 + lrow) * C + kb + 4 * q0];
        w1r = *(const float4*)&W1[(n0 + lrow) * C + kb + 4 * q0];
        if (DUAL)
            w2r = *(const float4*)&W2[(n0 + lrow) * C + kb + 4 * q0];
    };
    gload(0);

    // Split one float4 into hi(tf32)/lo(residual) with R6's fragment
    // permutation: quad q -> block s=q>>1, parity (q&1); word stride 2.
    const int dbase = (q0 >> 1) * BLK + lrow * 8 + (q0 & 1);
    auto stile = [&](int hibase, const float4& v) {
        uint32_t* dst = &sm[hibase + dbase];
        const float vv[4] = {v.x, v.y, v.z, v.w};
#pragma unroll
        for (int cc = 0; cc < 4; cc++) {
            const uint32_t hi = f2tf32(vv[cc]);
            const float    lo = vv[cc] - __uint_as_float(hi);
            dst[2 * cc]        = hi;
            dst[TIER + 2 * cc] = __float_as_uint(lo);
        }
    };

    // ---- compute mapping: warp tile m16 x n8 over k-half z ----
    const int M0 = (mw >> 2) * 16;
    const int N0 = (mw & 3) * 8;
    const int ar = (M0 + (lane >> 2)) * 8 + 2 * (lane & 3);
    const int br = (N0 + (lane >> 2)) * 8 + 2 * (lane & 3);

    float p[3][4] = {}, q[3][4] = {};

    for (int ch = 0; ch < NCH; ch++) {
        if (ch) __syncthreads();
        stile(A_HI,  xr);
        stile(B1_HI, w1r);
        if (DUAL) stile(B2_HI, w2r);
        __syncthreads();
        if (ch + 1 < NCH) gload((ch + 1) * KC);   // prefetch under compute

#pragma unroll
        for (int ss = 0; ss < 4; ss++) {
            const int o = (4 * z + ss) * BLK;
            const uint2 h02 = *(const uint2*)&sm[A_HI + o + ar];
            const uint2 h13 = *(const uint2*)&sm[A_HI + o + ar + 64];
            const uint2 l02 = *(const uint2*)&sm[A_HI + TIER + o + ar];
            const uint2 l13 = *(const uint2*)&sm[A_HI + TIER + o + ar + 64];
            const uint32_t Ah[4] = {h02.x, h13.x, h02.y, h13.y};
            const uint32_t Al[4] = {l02.x, l13.x, l02.y, l13.y};

            const uint2 b1h = *(const uint2*)&sm[B1_HI + o + br];
            const uint2 b1l = *(const uint2*)&sm[B1_HI + TIER + o + br];
            const uint32_t B1h[2] = {b1h.x, b1h.y};
            const uint32_t B1l[2] = {b1l.x, b1l.y};

            mma8(p[0], Ah, B1h);
            mma8(p[1], Ah, B1l);
            mma8(p[2], Al, B1h);

            if (DUAL) {
                const uint2 b2h = *(const uint2*)&sm[B2_HI + o + br];
                const uint2 b2l = *(const uint2*)&sm[B2_HI + TIER + o + br];
                const uint32_t B2h[2] = {b2h.x, b2h.y};
                const uint32_t B2l[2] = {b2l.x, b2l.y};
                mma8(q[0], Ah, B2h);
                mma8(q[1], Ah, B2l);
                mma8(q[2], Al, B2h);
            }
        }
    }

    // ---- merge k-halves, then (optional) product, store ----
    float P[4], Q[4];
#pragma unroll
    for (int i = 0; i < 4; i++) {
        P[i] = p[0][i] + p[1][i] + p[2][i];
        if (DUAL) Q[i] = q[0][i] + q[1][i] + q[2][i];
    }

    __syncthreads();                       // smem tiles no longer needed
    float4* red = (float4*)sm;             // [256] P-plane, [256] Q-plane
    if (z == 1) {
        const int e = tid - 256;           // matches (mw, lane) of z=0 peer
        red[e] = make_float4(P[0], P[1], P[2], P[3]);
        if (DUAL) red[256 + e] = make_float4(Q[0], Q[1], Q[2], Q[3]);
    }
    __syncthreads();
    if (z == 0) {
        const float4 po = red[tid];
        P[0] += po.x; P[1] += po.y; P[2] += po.z; P[3] += po.w;
        if (DUAL) {
            const float4 qo = red[256 + tid];
            Q[0] += qo.x; Q[1] += qo.y; Q[2] += qo.z; Q[3] += qo.w;
        }
        const int row = i0 + M0 + (lane >> 2);
        const int col = n0 + N0 + 2 * (lane & 3);
        float2 v0, v1;
        if (DUAL) {
            v0 = make_float2(P[0] * Q[0], P[1] * Q[1]);
            v1 = make_float2(P[2] * Q[2], P[3] * Q[3]);
        } else {
            v0 = make_float2(P[0], P[1]);
            v1 = make_float2(P[2], P[3]);
        }
        *(float2*)&OUT[ row      * C + col] = v0;
        *(float2*)&OUT[(row + 8) * C + col] = v1;
    }
}

extern "C" void kernel_launch(void* const* d_in, const int* in_sizes, int n_in,
                              void* d_out, int out_size)
{
    // metadata order: x, Wq, Wk1, Wk2, Wv1, Wv2, Wc
    const float* x   = (const float*)d_in[0];
    const float* Wv1 = (const float*)d_in[4];
    const float* Wv2 = (const float*)d_in[5];
    const float* Wc  = (const float*)d_in[6];
    float* out = (float*)d_out;

    float* tmp = nullptr;
    cudaGetSymbolAddress((void**)&tmp, g_tmp);

    const int sm1 = 6 * TIER * 4;   // 50688 B
    const int sm2 = 4 * TIER * 4;   // 33792 B
    cudaFuncSetAttribute(gemm_mma_kernel<true>,
                         cudaFuncAttributeMaxDynamicSharedMemorySize, sm1);
    cudaFuncSetAttribute(gemm_mma_kernel<false>,
                         cudaFuncAttributeMaxDynamicSharedMemorySize, sm2);

    dim3 grid(T / 32, C / 32);   // 8 x 16 = 128 CTAs
    gemm_mma_kernel<true ><<<grid, 512, sm1>>>(x,   Wv1, Wv2,     tmp);
    gemm_mma_kernel<false><<<grid, 512, sm2>>>(tmp, Wc,  nullptr, out);
}

// round 10
// speedup vs baseline: 2.1461x; 1.3735x over previous
#include <cuda_runtime.h>
#include <cstdint>

// TrueHigherOrderAttention — degenerate-mask reduction.
// The reference mask forces j==i and k==i, so the (j,k) softmax is an exact
// one-hot at (i,i,i):   out = ((x @ Wv1^T) .* (x @ Wv2^T)) @ Wc^T
//
// R9: R6 skeleton (21.3us: 256 threads, 8 warps 2mx4n, m16n8k8 3xTF32,
// BLK=258 conflict-free STS) + two serialization fixes:
//   (a) double-buffered smem: ONE sync per chunk; the hi/lo split + STS of
//       chunk i+1 overlaps the MMA phase of chunk i.
//   (b) explicit fragment software-pipeline: step s+1 fragments are loaded
//       before step s MMAs issue (two register Frag sets), hiding LDS latency
//       under independent tensor ops.

constexpr int T    = 256;
constexpr int C    = 512;
constexpr int KC   = 64;
constexpr int NCH  = 8;          // 512 / 64
constexpr int BLK  = 258;        // words per 8-k block (32 rows x 8 + pad 2)
constexpr int TIER = 8 * BLK;    // hi -> lo offset within a tile

__device__ float g_tmp[T * C];

__device__ __forceinline__ uint32_t f2tf32(float x)
{
    uint32_t r;
    asm("cvt.rna.tf32.f32 %0, %1;" : "=r"(r) : "f"(x));
    return r;
}

__device__ __forceinline__ void mma8(float* d, const uint32_t* a, const uint32_t* b)
{
    asm("mma.sync.aligned.m16n8k8.row.col.f32.tf32.tf32.f32 "
        "{%0,%1,%2,%3}, {%4,%5,%6,%7}, {%8,%9}, {%0,%1,%2,%3};"
        : "+f"(d[0]), "+f"(d[1]), "+f"(d[2]), "+f"(d[3])
        : "r"(a[0]), "r"(a[1]), "r"(a[2]), "r"(a[3]),
          "r"(b[0]), "r"(b[1]));
}

// OUT = (X @ W1^T) [ .* (X @ W2^T) if DUAL ]  on a 32x32 tile, 3xTF32.
// X: [M x C] row-major; W: [C x C] row-major (output col n = row n of W).
template <bool DUAL>
__global__ __launch_bounds__(256)
void gemm_mma_kernel(const float* __restrict__ X,
                     const float* __restrict__ W1,
                     const float* __restrict__ W2,
                     float* __restrict__ OUT)
{
    extern __shared__ uint32_t sm[];
    constexpr int NTILE = DUAL ? 3 : 2;
    constexpr int BUFW  = 2 * NTILE * TIER;   // words per double-buffer half

    const int i0   = blockIdx.x * 32;
    const int n0   = blockIdx.y * 32;
    const int tid  = threadIdx.x;
    const int lane = tid & 31;
    const int wid  = tid >> 5;

    // ---- loader mapping (R6, verified conflict-free STS with BLK=258) ----
    const int lrow = tid >> 3;   // 0..31
    const int j0   = tid & 7;    // float4 quad; +8 on second iter

    float4 xr[2], w1r[2], w2r[2];
    auto gload = [&](int kb) {
#pragma unroll
        for (int it = 0; it < 2; it++) {
            const int j = j0 + 8 * it;
            xr [it] = *(const float4*)&X [(i0 + lrow) * C + kb + 4 * j];
            w1r[it] = *(const float4*)&W1[(n0 + lrow) * C + kb + 4 * j];
            if (DUAL)
                w2r[it] = *(const float4*)&W2[(n0 + lrow) * C + kb + 4 * j];
        }
    };

    auto stile = [&](uint32_t* base, const float4& v, int j) {
        uint32_t* dst = base + (j >> 1) * BLK + lrow * 8 + (j & 1);
        const float vv[4] = {v.x, v.y, v.z, v.w};
#pragma unroll
        for (int cc = 0; cc < 4; cc++) {
            const uint32_t hi = f2tf32(vv[cc]);
            dst[2 * cc]        = hi;
            dst[TIER + 2 * cc] = __float_as_uint(vv[cc] - __uint_as_float(hi));
        }
    };

    auto split_sts = [&](uint32_t* buf) {
#pragma unroll
        for (int it = 0; it < 2; it++) {
            const int j = j0 + 8 * it;
            stile(buf,            xr [it], j);
            stile(buf + 2 * TIER, w1r[it], j);
            if (DUAL) stile(buf + 4 * TIER, w2r[it], j);
        }
    };

    // ---- compute mapping: 8 warps = 2(m) x 4(n); warp tile m16 x n8 ----
    const int M0 = (wid >> 2) * 16;
    const int N0 = (wid & 3) * 8;
    const int ar = (M0 + (lane >> 2)) * 8 + 2 * (lane & 3);
    const int br = (N0 + (lane >> 2)) * 8 + 2 * (lane & 3);

    struct Frag {
        uint32_t Ah[4], Al[4], B1h[2], B1l[2], B2h[2], B2l[2];
    };
    Frag fr[2];

    auto ldfrag = [&](const uint32_t* buf, int s, Frag& f) {
        const int o = s * BLK;
        const uint2 h02 = *(const uint2*)&buf[o + ar];
        const uint2 h13 = *(const uint2*)&buf[o + ar + 64];
        const uint2 l02 = *(const uint2*)&buf[TIER + o + ar];
        const uint2 l13 = *(const uint2*)&buf[TIER + o + ar + 64];
        f.Ah[0] = h02.x; f.Ah[1] = h13.x; f.Ah[2] = h02.y; f.Ah[3] = h13.y;
        f.Al[0] = l02.x; f.Al[1] = l13.x; f.Al[2] = l02.y; f.Al[3] = l13.y;
        const uint2 b1h = *(const uint2*)&buf[2 * TIER + o + br];
        const uint2 b1l = *(const uint2*)&buf[3 * TIER + o + br];
        f.B1h[0] = b1h.x; f.B1h[1] = b1h.y;
        f.B1l[0] = b1l.x; f.B1l[1] = b1l.y;
        if (DUAL) {
            const uint2 b2h = *(const uint2*)&buf[4 * TIER + o + br];
            const uint2 b2l = *(const uint2*)&buf[5 * TIER + o + br];
            f.B2h[0] = b2h.x; f.B2h[1] = b2h.y;
            f.B2l[0] = b2l.x; f.B2l[1] = b2l.y;
        }
    };

    float p[3][4] = {}, q[3][4] = {};

    // ---- prologue: fill buffer 0 ----
    gload(0);
    split_sts(sm);
    __syncthreads();

    for (int ch = 0; ch < NCH; ch++) {
        uint32_t* buf = sm + (ch & 1) * BUFW;
        if (ch + 1 < NCH) gload((ch + 1) * KC);   // LDG early, long latency

        ldfrag(buf, 0, fr[0]);
#pragma unroll
        for (int s = 0; s < 8; s++) {
            if (s < 7) ldfrag(buf, s + 1, fr[(s + 1) & 1]);
            Frag& f = fr[s & 1];
            mma8(p[0], f.Ah, f.B1h);
            if (DUAL) mma8(q[0], f.Ah, f.B2h);
            mma8(p[1], f.Ah, f.B1l);
            if (DUAL) mma8(q[1], f.Ah, f.B2l);
            mma8(p[2], f.Al, f.B1h);
            if (DUAL) mma8(q[2], f.Al, f.B2h);
        }

        if (ch + 1 < NCH) {
            split_sts(sm + ((ch + 1) & 1) * BUFW);  // overlaps nothing behind a bar
            __syncthreads();
        }
    }

    // ---- epilogue: merge decomposition terms, (optional) product, store ----
    float P[4], Q[4];
#pragma unroll
    for (int i = 0; i < 4; i++) {
        P[i] = p[0][i] + p[1][i] + p[2][i];
        if (DUAL) Q[i] = q[0][i] + q[1][i] + q[2][i];
    }
    const int row = i0 + M0 + (lane >> 2);
    const int col = n0 + N0 + 2 * (lane & 3);
    float2 v0, v1;
    if (DUAL) {
        v0 = make_float2(P[0] * Q[0], P[1] * Q[1]);
        v1 = make_float2(P[2] * Q[2], P[3] * Q[3]);
    } else {
        v0 = make_float2(P[0], P[1]);
        v1 = make_float2(P[2], P[3]);
    }
    *(float2*)&OUT[ row      * C + col] = v0;
    *(float2*)&OUT[(row + 8) * C + col] = v1;
}

extern "C" void kernel_launch(void* const* d_in, const int* in_sizes, int n_in,
                              void* d_out, int out_size)
{
    // metadata order: x, Wq, Wk1, Wk2, Wv1, Wv2, Wc
    const float* x   = (const float*)d_in[0];
    const float* Wv1 = (const float*)d_in[4];
    const float* Wv2 = (const float*)d_in[5];
    const float* Wc  = (const float*)d_in[6];
    float* out = (float*)d_out;

    float* tmp = nullptr;
    cudaGetSymbolAddress((void**)&tmp, g_tmp);

    const int sm1 = 2 * 6 * TIER * 4;   // 99072 B  (double-buffered, 3 tiles)
    const int sm2 = 2 * 4 * TIER * 4;   // 66048 B  (double-buffered, 2 tiles)
    cudaFuncSetAttribute(gemm_mma_kernel<true>,
                         cudaFuncAttributeMaxDynamicSharedMemorySize, sm1);
    cudaFuncSetAttribute(gemm_mma_kernel<false>,
                         cudaFuncAttributeMaxDynamicSharedMemorySize, sm2);

    dim3 grid(T / 32, C / 32);   // 8 x 16 = 128 CTAs
    gemm_mma_kernel<true ><<<grid, 256, sm1>>>(x,   Wv1, Wv2,     tmp);
    gemm_mma_kernel<false><<<grid, 256, sm2>>>(tmp, Wc,  nullptr, out);
}